// round 14
// baseline (speedup 1.0000x reference)
#include <cuda_runtime.h>
#include <cuda_fp16.h>
#include <cstdint>

#define D 128
#define MAXN 50000
#define MAXE 800000
#define BUILD_BLOCKS 592

// ---------------- scratch (device globals; no allocations allowed) ----------
__device__ float  g_AX [MAXN * D];
__device__ __half g_DBh[MAXN * 2 * D];   // per node: 32 groups of [4x 0.5*D half | 4x B half]
__device__ __half g_EXh[MAXN * D];       // 0.5 * EX
__device__ __half g_Xh [MAXN * D];       // X, fp16, quad-packed words
__device__ __half g_WTh[4 * D * D];      // W^T, fp16, quad-packed words
__device__ float  g_H  [MAXN * D];
__device__ int    g_cnt[MAXN];
__device__ int    g_off[MAXN + 1];
__device__ int    g_csr[MAXE];           // BYTE offsets into g_DBh (src * 512)
__device__ int    g_bsum[256];
__device__ int    g_bpre[256];
__device__ float  g_colsum[D];
__device__ float  g_colsq [D];
__device__ unsigned          g_bar_cnt = 0;
__device__ volatile unsigned g_bar_gen = 0;

// ---------------- static stream/event context (created at load, pre-capture) -
namespace {
struct Ctx {
    cudaStream_t sb;
    cudaEvent_t ev_fork, ev_prep, ev_bA, ev_bB;
    Ctx() {
        cudaStreamCreateWithFlags(&sb, cudaStreamNonBlocking);
        cudaEventCreateWithFlags(&ev_fork, cudaEventDisableTiming);
        cudaEventCreateWithFlags(&ev_prep, cudaEventDisableTiming);
        cudaEventCreateWithFlags(&ev_bA, cudaEventDisableTiming);
        cudaEventCreateWithFlags(&ev_bB, cudaEventDisableTiming);
    }
};
Ctx g_ctx;
}

// ---------------- helpers ----------------------------------------------------
__device__ __forceinline__ __half2 u2h2(uint32_t u) {
    return *reinterpret_cast<__half2*>(&u);
}
// sigmoid(2x) for packed half2 x: 0.5*tanh(x)+0.5 (inputs pre-scaled by 0.5)
__device__ __forceinline__ __half2 gate2(uint32_t dh, __half2 e, __half2 h05) {
    __half2 s = __hadd2(u2h2(dh), e);
    uint32_t t;
    asm("tanh.approx.f16x2 %0, %1;" : "=r"(t) : "r"(*reinterpret_cast<uint32_t*>(&s)));
    return __hfma2(u2h2(t), h05, h05);
}
// quad-packed physical position of half2-word w within its 16-word supergroup
__device__ __forceinline__ int qposw(int w) {
    return ((w >> 4) << 4) + ((w & 3) << 2) + ((w >> 2) & 3);
}
// physical HALF index for logical k (word = k/2, lane = k%2)
__device__ __forceinline__ int qposh(int k) {
    return (qposw(k >> 1) << 1) + (k & 1);
}
__device__ __forceinline__ void mma_f16(float* a4,
                                        uint32_t a0, uint32_t a1, uint32_t a2, uint32_t a3,
                                        uint32_t b0, uint32_t b1) {
    asm volatile(
        "mma.sync.aligned.m16n8k16.row.col.f32.f16.f16.f32 "
        "{%0,%1,%2,%3}, {%4,%5,%6,%7}, {%8,%9}, {%0,%1,%2,%3};"
        : "+f"(a4[0]), "+f"(a4[1]), "+f"(a4[2]), "+f"(a4[3])
        : "r"(a0), "r"(a1), "r"(a2), "r"(a3), "r"(b0), "r"(b1));
}

// software grid barrier — used ONLY by buildA (runs alone; prep kernels on the
// side stream terminate, so co-residency of all 592 blocks is preserved)
__device__ __forceinline__ void grid_barrier() {
    __syncthreads();
    if (threadIdx.x == 0) {
        __threadfence();
        unsigned gen = g_bar_gen;
        if (atomicAdd(&g_bar_cnt, 1u) == BUILD_BLOCKS - 1) {
            g_bar_cnt = 0;
            __threadfence();
            g_bar_gen = gen + 1;
        } else {
            while (g_bar_gen == gen) {}
        }
        __threadfence();
    }
    __syncthreads();
}

// ---------------- kernel 1 (side): transpose + fp16 + quad-pack the 4 weights -
__global__ void prepw_kernel(const float* __restrict__ WA, const float* __restrict__ WB,
                             const float* __restrict__ WD, const float* __restrict__ WE)
{
    __shared__ float t[32][33];
    const float* W;
    switch (blockIdx.z) {
        case 0:  W = WA; break;
        case 1:  W = WB; break;
        case 2:  W = WD; break;
        default: W = WE; break;
    }
    int n0 = blockIdx.x * 32;
    int k0 = blockIdx.y * 32;
    for (int i = threadIdx.y; i < 32; i += 8)
        t[i][threadIdx.x] = W[(k0 + i) * D + n0 + threadIdx.x];
    __syncthreads();
    __half* out = g_WTh + blockIdx.z * D * D;
    for (int i = threadIdx.y; i < 32; i += 8) {
        float v = t[threadIdx.x][i];                 // W[k0+tx][n0+i]
        out[(n0 + i) * D + qposh(k0 + threadIdx.x)] = __float2half_rn(v);
    }
}

// ---------------- kernel 2 (side): convert X to fp16 quad-packed words --------
__global__ void prepx_kernel(const float* __restrict__ X, int n)
{
    uint32_t* out = reinterpret_cast<uint32_t*>(g_Xh);
    const float2* X2 = reinterpret_cast<const float2*>(X);
    int total = n * 64;                              // half2 words
    int tid = blockIdx.x * blockDim.x + threadIdx.x;
    int stride = gridDim.x * blockDim.x;
    for (int i = tid; i < total; i += stride) {
        int node = i >> 6;
        int w    = i & 63;
        float2 v = X2[i];
        __half2 h = __floats2half2_rn(v.x, v.y);
        out[node * 64 + qposw(w)] = *reinterpret_cast<uint32_t*>(&h);
    }
}

// ---------------- kernel 3 (main): buildA — zero + hist + scan -> g_off -------
__global__ __launch_bounds__(256, 4) void buildA_kernel(
    const int* __restrict__ dst, int n, int E)
{
    const int tid  = threadIdx.x;
    const int gtid = blockIdx.x * 256 + tid;
    const int nthreads = BUILD_BLOCKS * 256;

    for (int i = gtid; i < n; i += nthreads) g_cnt[i] = 0;
    if (gtid < D) { g_colsum[gtid] = 0.0f; g_colsq[gtid] = 0.0f; }
    if (gtid == nthreads - 1) g_off[n] = E;
    grid_barrier();

    for (int e = gtid; e < E; e += nthreads) atomicAdd(&g_cnt[dst[e]], 1);
    grid_barrier();

    __shared__ int s[256];
    const int myc = (gtid < n) ? g_cnt[gtid] : 0;
    s[tid] = myc;
    __syncthreads();
    #pragma unroll
    for (int d = 1; d < 256; d <<= 1) {
        int t = (tid >= d) ? s[tid - d] : 0;
        __syncthreads();
        s[tid] += t;
        __syncthreads();
    }
    const int incl = s[tid];
    const int nchunk = (n + 255) >> 8;
    if (tid == 255 && blockIdx.x < nchunk) g_bsum[blockIdx.x] = incl;
    grid_barrier();

    if (blockIdx.x == 0) {
        int v = (tid < nchunk) ? g_bsum[tid] : 0;
        s[tid] = v;
        __syncthreads();
        #pragma unroll
        for (int d = 1; d < 256; d <<= 1) {
            int t = (tid >= d) ? s[tid - d] : 0;
            __syncthreads();
            s[tid] += t;
            __syncthreads();
        }
        if (tid < nchunk) g_bpre[tid] = s[tid] - v;
    }
    grid_barrier();

    if (gtid < n) {
        g_off[gtid] = g_bpre[blockIdx.x] + incl - myc;   // exclusive prefix
        g_cnt[gtid] = 0;                                 // scatter cursor
    }
}

// ---------------- kernel 5 (side): buildB — scatter BYTE offsets into CSR -----
__global__ void buildB_kernel(const int* __restrict__ src,
                              const int* __restrict__ dst, int E)
{
    int e = blockIdx.x * blockDim.x + threadIdx.x;
    if (e < E) {
        int d0 = dst[e];
        int pos = g_off[d0] + atomicAdd(&g_cnt[d0], 1);
        g_csr[pos] = src[e] * (2 * D * (int)sizeof(__half));   // byte offset (x512)
    }
}

// ---------------- kernel 4 (PROFILED, main): fp16 tensor GEMM -----------------
// block tile 128M x 64N, warp tile 32x32. grid (rowtiles, 4 mats, 2 N-halves).
// smem: Xs 128x80w (40KB) + Ws 64x80w (20KB) = 60KB -> 3 blocks/SM.
#define SPADW 80
__global__ __launch_bounds__(256, 3) void gemm_kernel(
    const float* __restrict__ bA, const float* __restrict__ bB,
    const float* __restrict__ bD, const float* __restrict__ bE,
    int n)
{
    extern __shared__ uint32_t smw[];
    uint32_t* Xs = smw;                // [128][SPADW] half2 words
    uint32_t* Ws = smw + 128 * SPADW;  // [64][SPADW]

    const int tid  = threadIdx.x;
    const int mat  = blockIdx.y;
    const int nz   = blockIdx.z;        // N half: cols [nz*64, nz*64+64)
    const int row0 = blockIdx.x * 128;

    // copy X tile: 128 rows x 16 uint4
    {
        const uint4* Xg = reinterpret_cast<const uint4*>(g_Xh);
        #pragma unroll
        for (int i = 0; i < 8; i++) {
            int f  = tid + i * 256;      // [0,2048)
            int r  = f >> 4;
            int j  = f & 15;
            int gr = row0 + r;
            uint4 v = make_uint4(0u, 0u, 0u, 0u);
            if (gr < n) v = Xg[gr * 16 + j];
            *reinterpret_cast<uint4*>(&Xs[r * SPADW + j * 4]) = v;
        }
    }
    // copy W half-tile: 64 rows x 16 uint4 (rows nz*64 .. nz*64+63)
    {
        const uint4* Wg = reinterpret_cast<const uint4*>(g_WTh + mat * D * D) + nz * 64 * 16;
        #pragma unroll
        for (int i = 0; i < 4; i++) {
            int f  = tid + i * 256;      // [0,1024)
            int r  = f >> 4;
            int j  = f & 15;
            *reinterpret_cast<uint4*>(&Ws[r * SPADW + j * 4]) = Wg[f];
        }
    }
    __syncthreads();

    const int lane = tid & 31;
    const int warp = tid >> 5;
    const int m0   = (warp & 3) * 32;    // 4 m-positions
    const int nc0  = (warp >> 2) * 32;   // 2 n-positions (within the 64-half)
    const int r    = lane >> 2;
    const int c    = lane & 3;

    float acc0[4][4];   // rows m0 .. m0+15
    float acc1[4][4];   // rows m0+16 .. m0+31
    #pragma unroll
    for (int nt = 0; nt < 4; nt++)
        #pragma unroll
        for (int j = 0; j < 4; j++) { acc0[nt][j] = 0.0f; acc1[nt][j] = 0.0f; }

    #pragma unroll
    for (int sg = 0; sg < 4; sg++) {
        const int kb = sg * 16 + c * 4;
        uint4 A0 = *reinterpret_cast<const uint4*>(&Xs[(m0 + r     ) * SPADW + kb]);
        uint4 A1 = *reinterpret_cast<const uint4*>(&Xs[(m0 + r +  8) * SPADW + kb]);
        uint4 A2 = *reinterpret_cast<const uint4*>(&Xs[(m0 + r + 16) * SPADW + kb]);
        uint4 A3 = *reinterpret_cast<const uint4*>(&Xs[(m0 + r + 24) * SPADW + kb]);
        #pragma unroll
        for (int nt = 0; nt < 4; nt++) {
            uint4 B = *reinterpret_cast<const uint4*>(&Ws[(nc0 + nt * 8 + r) * SPADW + kb]);
            mma_f16(acc0[nt], A0.x, A1.x, A0.y, A1.y, B.x, B.y);
            mma_f16(acc1[nt], A2.x, A3.x, A2.y, A3.y, B.x, B.y);
            mma_f16(acc0[nt], A0.z, A1.z, A0.w, A1.w, B.z, B.w);
            mma_f16(acc1[nt], A2.z, A3.z, A2.w, A3.w, B.z, B.w);
        }
    }

    const float* bias = (mat == 0) ? bA : (mat == 1) ? bB : (mat == 2) ? bD : bE;
    const float osc = (mat >= 2) ? 0.5f : 1.0f;
    #pragma unroll
    for (int mt = 0; mt < 2; mt++) {
        float (*acc)[4] = mt ? acc1 : acc0;
        const int gr0 = row0 + m0 + mt * 16 + r;
        const int gr1 = gr0 + 8;
        #pragma unroll
        for (int nt = 0; nt < 4; nt++) {
            int col = nz * 64 + nc0 + nt * 8 + c * 2;
            float2 bv = *reinterpret_cast<const float2*>(&bias[col]);
            float2 o0 = make_float2((acc[nt][0] + bv.x) * osc, (acc[nt][1] + bv.y) * osc);
            float2 o1 = make_float2((acc[nt][2] + bv.x) * osc, (acc[nt][3] + bv.y) * osc);
            if (mat == 0) {
                if (gr0 < n) *reinterpret_cast<float2*>(&g_AX[gr0 * D + col]) = o0;
                if (gr1 < n) *reinterpret_cast<float2*>(&g_AX[gr1 * D + col]) = o1;
            } else if (mat == 3) {
                if (gr0 < n) *reinterpret_cast<__half2*>(&g_EXh[gr0 * D + col]) = __floats2half2_rn(o0.x, o0.y);
                if (gr1 < n) *reinterpret_cast<__half2*>(&g_EXh[gr1 * D + col]) = __floats2half2_rn(o1.x, o1.y);
            } else {
                int po = ((col >> 2) << 3) + (col & 3) + (mat == 1 ? 4 : 0);
                if (gr0 < n) *reinterpret_cast<__half2*>(&g_DBh[gr0 * 2 * D + po]) = __floats2half2_rn(o0.x, o0.y);
                if (gr1 < n) *reinterpret_cast<__half2*>(&g_DBh[gr1 * 2 * D + po]) = __floats2half2_rn(o1.x, o1.y);
            }
        }
    }
}

// ---------------- kernel 6: per-node aggregation + H + BN partials ------------
// csr holds BYTE offsets; next-group indices prefetched. 5 blocks/SM forced.
__global__ __launch_bounds__(256, 5) void agg_kernel(const float* __restrict__ X, int n)
{
    __shared__ float ssum[D];
    __shared__ float ssq [D];
    const int tid = threadIdx.x;
    if (tid < D) { ssum[tid] = 0.0f; ssq[tid] = 0.0f; }
    __syncthreads();

    const __half2 h05 = __floats2half2_rn(0.5f, 0.5f);
    const int lane = tid & 31;
    const int warp = tid >> 5;
    const int off  = lane * 4;
    const char* dbbase = reinterpret_cast<const char*>(g_DBh) + lane * 16;
    const int gw   = blockIdx.x * 8 + warp;
    const int nw   = gridDim.x * 8;

    float4 csum = make_float4(0.f, 0.f, 0.f, 0.f);
    float4 csq  = make_float4(0.f, 0.f, 0.f, 0.f);

    for (int node = gw; node < n; node += nw) {
        int beg = g_off[node];
        int end = g_off[node + 1];
        int base = node * D + off;
        float4 h;
        if (end > beg) {
            uint2 eu = *reinterpret_cast<const uint2*>(&g_EXh[base]);
            __half2 e0 = u2h2(eu.x), e1 = u2h2(eu.y);
            float2 num0 = make_float2(0.f, 0.f), num1 = make_float2(0.f, 0.f);
            float2 den0 = make_float2(0.f, 0.f), den1 = make_float2(0.f, 0.f);
            int j = beg;
            int c0 = 0, c1 = 0, c2 = 0, c3 = 0;
            if (j + 3 < end) {
                c0 = g_csr[j]; c1 = g_csr[j + 1]; c2 = g_csr[j + 2]; c3 = g_csr[j + 3];
            }
            while (j + 3 < end) {
                int p0 = 0, p1 = 0, p2 = 0, p3 = 0;
                if (j + 7 < end) {
                    p0 = g_csr[j + 4]; p1 = g_csr[j + 5];
                    p2 = g_csr[j + 6]; p3 = g_csr[j + 7];
                }
                uint4 q0 = *reinterpret_cast<const uint4*>(dbbase + c0);
                uint4 q1 = *reinterpret_cast<const uint4*>(dbbase + c1);
                uint4 q2 = *reinterpret_cast<const uint4*>(dbbase + c2);
                uint4 q3 = *reinterpret_cast<const uint4*>(dbbase + c3);
                __half2 sg00 = gate2(q0.x, e0, h05), sg01 = gate2(q0.y, e1, h05);
                __half2 sg10 = gate2(q1.x, e0, h05), sg11 = gate2(q1.y, e1, h05);
                __half2 sg20 = gate2(q2.x, e0, h05), sg21 = gate2(q2.y, e1, h05);
                __half2 sg30 = gate2(q3.x, e0, h05), sg31 = gate2(q3.y, e1, h05);
                __half2 hd0 = __hadd2(__hadd2(sg00, sg10), __hadd2(sg20, sg30));
                __half2 hd1 = __hadd2(__hadd2(sg01, sg11), __hadd2(sg21, sg31));
                __half2 hn0 = __hadd2(__hadd2(__hmul2(sg00, u2h2(q0.z)), __hmul2(sg10, u2h2(q1.z))),
                                      __hadd2(__hmul2(sg20, u2h2(q2.z)), __hmul2(sg30, u2h2(q3.z))));
                __half2 hn1 = __hadd2(__hadd2(__hmul2(sg01, u2h2(q0.w)), __hmul2(sg11, u2h2(q1.w))),
                                      __hadd2(__hmul2(sg21, u2h2(q2.w)), __hmul2(sg31, u2h2(q3.w))));
                float2 f;
                f = __half22float2(hd0); den0.x += f.x; den0.y += f.y;
                f = __half22float2(hd1); den1.x += f.x; den1.y += f.y;
                f = __half22float2(hn0); num0.x += f.x; num0.y += f.y;
                f = __half22float2(hn1); num1.x += f.x; num1.y += f.y;
                c0 = p0; c1 = p1; c2 = p2; c3 = p3;
                j += 4;
            }
            for (; j < end; j++) {
                int s = g_csr[j];
                uint4 q = *reinterpret_cast<const uint4*>(dbbase + s);
                __half2 sg0 = gate2(q.x, e0, h05), sg1 = gate2(q.y, e1, h05);
                float2 f;
                f = __half22float2(sg0); den0.x += f.x; den0.y += f.y;
                f = __half22float2(sg1); den1.x += f.x; den1.y += f.y;
                f = __half22float2(__hmul2(sg0, u2h2(q.z))); num0.x += f.x; num0.y += f.y;
                f = __half22float2(__hmul2(sg1, u2h2(q.w))); num1.x += f.x; num1.y += f.y;
            }
            float4 ax = *reinterpret_cast<const float4*>(&g_AX[base]);
            h.x = ax.x + num0.x / den0.x;
            h.y = ax.y + num0.y / den0.y;
            h.z = ax.z + num1.x / den1.x;
            h.w = ax.w + num1.y / den1.y;
        } else {
            h = *reinterpret_cast<const float4*>(&X[base]);
        }
        *reinterpret_cast<float4*>(&g_H[base]) = h;
        csum.x += h.x; csum.y += h.y; csum.z += h.z; csum.w += h.w;
        csq.x  = fmaf(h.x, h.x, csq.x);
        csq.y  = fmaf(h.y, h.y, csq.y);
        csq.z  = fmaf(h.z, h.z, csq.z);
        csq.w  = fmaf(h.w, h.w, csq.w);
    }

    atomicAdd(&ssum[off + 0], csum.x); atomicAdd(&ssum[off + 1], csum.y);
    atomicAdd(&ssum[off + 2], csum.z); atomicAdd(&ssum[off + 3], csum.w);
    atomicAdd(&ssq [off + 0], csq.x);  atomicAdd(&ssq [off + 1], csq.y);
    atomicAdd(&ssq [off + 2], csq.z);  atomicAdd(&ssq [off + 3], csq.w);
    __syncthreads();
    if (tid < D) {
        atomicAdd(&g_colsum[tid], ssum[tid]);
        atomicAdd(&g_colsq [tid], ssq [tid]);
    }
}

// ---------------- kernel 7: epilogue with inline BN stats ---------------------
__global__ __launch_bounds__(256) void final_kernel(
    const float* __restrict__ X, const float* __restrict__ gamma,
    const float* __restrict__ beta, float* __restrict__ out,
    int n, float inv_n, float eps_n2)
{
    __shared__ float sc[D];
    __shared__ float sh[D];
    if (threadIdx.x < D) {
        int d = threadIdx.x;
        float mean = g_colsum[d] * inv_n;
        float var  = g_colsq[d] * inv_n - mean * mean;
        float istd = rsqrtf(var + eps_n2);
        float s    = istd * gamma[d];
        sc[d] = s;
        sh[d] = beta[d] - mean * s;
    }
    __syncthreads();

    int total4 = n * (D / 4);
    const float4* X4 = reinterpret_cast<const float4*>(X);
    const float4* H4 = reinterpret_cast<const float4*>(g_H);
    float4* O4 = reinterpret_cast<float4*>(out);

    int tid = blockIdx.x * blockDim.x + threadIdx.x;
    int stride = gridDim.x * blockDim.x;
    for (int i = tid; i < total4; i += stride) {
        int d = (i & 31) * 4;
        float4 h = H4[i];
        float4 x = X4[i];
        float4 o;
        o.x = x.x + fmaxf(0.0f, fmaf(h.x, sc[d + 0], sh[d + 0]));
        o.y = x.y + fmaxf(0.0f, fmaf(h.y, sc[d + 1], sh[d + 1]));
        o.z = x.z + fmaxf(0.0f, fmaf(h.z, sc[d + 2], sh[d + 2]));
        o.w = x.w + fmaxf(0.0f, fmaf(h.w, sc[d + 3], sh[d + 3]));
        O4[i] = o;
    }
}

// ---------------- launch -----------------------------------------------------
extern "C" void kernel_launch(void* const* d_in, const int* in_sizes, int n_in,
                              void* d_out, int out_size)
{
    const float* X     = (const float*)d_in[0];
    const float* W_A   = (const float*)d_in[1];
    const float* b_A   = (const float*)d_in[2];
    const float* W_B   = (const float*)d_in[3];
    const float* b_B   = (const float*)d_in[4];
    const float* W_D   = (const float*)d_in[5];
    const float* b_D   = (const float*)d_in[6];
    const float* W_E   = (const float*)d_in[7];
    const float* b_E   = (const float*)d_in[8];
    const float* gamma = (const float*)d_in[9];
    const float* beta  = (const float*)d_in[10];
    const int*   src   = (const int*)d_in[11];
    const int*   dst   = (const int*)d_in[12];

    const int n = in_sizes[0] / D;
    const int E = in_sizes[11];
    const float inv_n  = 1.0f / (float)n;
    const float eps_n2 = 1e-5f * (float)n * (float)n;

    // fork side stream
    cudaEventRecord(g_ctx.ev_fork, 0);
    cudaStreamWaitEvent(g_ctx.sb, g_ctx.ev_fork, 0);

    // 1,2 (side): weight prep + X conversion — overlap with buildA
    prepw_kernel<<<dim3(4, 4, 4), dim3(32, 8), 0, g_ctx.sb>>>(W_A, W_B, W_D, W_E);
    prepx_kernel<<<296, 256, 0, g_ctx.sb>>>(X, n);
    cudaEventRecord(g_ctx.ev_prep, g_ctx.sb);

    // 3 (main): hist + scan (persistent grid-barrier kernel)
    buildA_kernel<<<BUILD_BLOCKS, 256>>>(dst, n, E);
    cudaEventRecord(g_ctx.ev_bA, 0);

    // 4 (main, profiled): fp16 GEMM — needs prep done
    cudaStreamWaitEvent(0, g_ctx.ev_prep, 0);
    static const int smem_bytes = (128 + 64) * SPADW * (int)sizeof(uint32_t);
    cudaFuncSetAttribute(gemm_kernel,
                         cudaFuncAttributeMaxDynamicSharedMemorySize, smem_bytes);
    gemm_kernel<<<dim3((n + 127) / 128, 4, 2), 256, smem_bytes>>>(b_A, b_B, b_D, b_E, n);

    // 5 (side): scatter — needs buildA; overlaps GEMM
    cudaStreamWaitEvent(g_ctx.sb, g_ctx.ev_bA, 0);
    buildB_kernel<<<(E + 255) / 256, 256, 0, g_ctx.sb>>>(src, dst, E);
    cudaEventRecord(g_ctx.ev_bB, g_ctx.sb);

    // 6 (main): aggregation — needs gemm (stream) + buildB (event)
    cudaStreamWaitEvent(0, g_ctx.ev_bB, 0);
    agg_kernel<<<1480, 256>>>(X, n);

    // 7 (main): epilogue with inline stats
    final_kernel<<<1024, 256>>>(X, gamma, beta, (float*)d_out, n, inv_n, eps_n2);
}

// round 16
// speedup vs baseline: 1.0245x; 1.0245x over previous
#include <cuda_runtime.h>
#include <cuda_fp16.h>
#include <cstdint>

#define D 128
#define MAXN 50000
#define MAXE 800000
#define SCAN_BLK 1024

// ---------------- scratch (device globals; no allocations allowed) ----------
__device__ float  g_AX [MAXN * D];
__device__ __half g_DBh[MAXN * 2 * D];   // per node: 32 groups of [4x 0.5*D half | 4x B half]
__device__ __half g_EXh[MAXN * D];       // 0.5 * EX
__device__ __half g_Xh [MAXN * D];       // X, fp16, quad-packed words
__device__ __half g_WTh[4 * D * D];      // W^T, fp16, quad-packed words
__device__ __half g_Hh [MAXN * D];       // H, fp16
__device__ int    g_cnt[MAXN];
__device__ int    g_off[MAXN + 1];
__device__ int    g_csr[MAXE];           // BYTE offsets into g_DBh (src * 512)
__device__ int    g_bsum[64];
__device__ int    g_bpre[64];
__device__ float  g_colsum[D];
__device__ float  g_colsq [D];

// ---------------- static stream/event context (created at load, pre-capture) -
namespace {
struct Ctx {
    cudaStream_t sb;
    cudaEvent_t ev_fork, ev_prep, ev_bB;
    Ctx() {
        cudaStreamCreateWithFlags(&sb, cudaStreamNonBlocking);
        cudaEventCreateWithFlags(&ev_fork, cudaEventDisableTiming);
        cudaEventCreateWithFlags(&ev_prep, cudaEventDisableTiming);
        cudaEventCreateWithFlags(&ev_bB, cudaEventDisableTiming);
    }
};
Ctx g_ctx;
}

// ---------------- helpers ----------------------------------------------------
__device__ __forceinline__ __half2 u2h2(uint32_t u) {
    return *reinterpret_cast<__half2*>(&u);
}
// sigmoid(2x) for packed half2 x: 0.5*tanh(x)+0.5 (inputs pre-scaled by 0.5)
__device__ __forceinline__ __half2 gate2(uint32_t dh, __half2 e, __half2 h05) {
    __half2 s = __hadd2(u2h2(dh), e);
    uint32_t t;
    asm("tanh.approx.f16x2 %0, %1;" : "=r"(t) : "r"(*reinterpret_cast<uint32_t*>(&s)));
    return __hfma2(u2h2(t), h05, h05);
}
// quad-packed physical position of half2-word w within its 16-word supergroup
__device__ __forceinline__ int qposw(int w) {
    return ((w >> 4) << 4) + ((w & 3) << 2) + ((w >> 2) & 3);
}
// physical HALF index for logical k (word = k/2, lane = k%2)
__device__ __forceinline__ int qposh(int k) {
    return (qposw(k >> 1) << 1) + (k & 1);
}
__device__ __forceinline__ void mma_f16(float* a4,
                                        uint32_t a0, uint32_t a1, uint32_t a2, uint32_t a3,
                                        uint32_t b0, uint32_t b1) {
    asm volatile(
        "mma.sync.aligned.m16n8k16.row.col.f32.f16.f16.f32 "
        "{%0,%1,%2,%3}, {%4,%5,%6,%7}, {%8,%9}, {%0,%1,%2,%3};"
        : "+f"(a4[0]), "+f"(a4[1]), "+f"(a4[2]), "+f"(a4[3])
        : "r"(a0), "r"(a1), "r"(a2), "r"(a3), "r"(b0), "r"(b1));
}

// ---------------- kernel 1 (side): zero counters + BN partials ----------------
__global__ void zero_kernel(int n, int E) {
    int tid = blockIdx.x * blockDim.x + threadIdx.x;
    int stride = gridDim.x * blockDim.x;
    for (int i = tid; i < n; i += stride) g_cnt[i] = 0;
    if (tid < D) { g_colsum[tid] = 0.0f; g_colsq[tid] = 0.0f; }
    if (tid == 0) g_off[n] = E;
}

// ---------------- kernel 2 (side): transpose + fp16 + quad-pack weights -------
__global__ void prepw_kernel(const float* __restrict__ WA, const float* __restrict__ WB,
                             const float* __restrict__ WD, const float* __restrict__ WE)
{
    __shared__ float t[32][33];
    const float* W;
    switch (blockIdx.z) {
        case 0:  W = WA; break;
        case 1:  W = WB; break;
        case 2:  W = WD; break;
        default: W = WE; break;
    }
    int n0 = blockIdx.x * 32;
    int k0 = blockIdx.y * 32;
    for (int i = threadIdx.y; i < 32; i += 8)
        t[i][threadIdx.x] = W[(k0 + i) * D + n0 + threadIdx.x];
    __syncthreads();
    __half* out = g_WTh + blockIdx.z * D * D;
    for (int i = threadIdx.y; i < 32; i += 8) {
        float v = t[threadIdx.x][i];                 // W[k0+tx][n0+i]
        out[(n0 + i) * D + qposh(k0 + threadIdx.x)] = __float2half_rn(v);
    }
}

// ---------------- kernel 3 (side): convert X to fp16 quad-packed words --------
__global__ void prepx_kernel(const float* __restrict__ X, int n)
{
    uint32_t* out = reinterpret_cast<uint32_t*>(g_Xh);
    const float2* X2 = reinterpret_cast<const float2*>(X);
    int total = n * 64;                              // half2 words
    int tid = blockIdx.x * blockDim.x + threadIdx.x;
    int stride = gridDim.x * blockDim.x;
    for (int i = tid; i < total; i += stride) {
        int node = i >> 6;
        int w    = i & 63;
        float2 v = X2[i];
        __half2 h = __floats2half2_rn(v.x, v.y);
        out[node * 64 + qposw(w)] = *reinterpret_cast<uint32_t*>(&h);
    }
}

// ---------------- kernel 4 (PROFILED, main): fp16 tensor GEMM -----------------
#define SPADW 80
__global__ __launch_bounds__(256, 2) void gemm_kernel(
    const float* __restrict__ bA, const float* __restrict__ bB,
    const float* __restrict__ bD, const float* __restrict__ bE,
    int n)
{
    extern __shared__ uint32_t smw[];
    uint32_t* Xs = smw;                // [128][SPADW] half2 words
    uint32_t* Ws = smw + 128 * SPADW;

    const int tid  = threadIdx.x;
    const int mat  = blockIdx.y;
    const int row0 = blockIdx.x * 128;

    {
        const uint4* Xg = reinterpret_cast<const uint4*>(g_Xh);
        const uint4* Wg = reinterpret_cast<const uint4*>(g_WTh + mat * D * D);
        #pragma unroll
        for (int i = 0; i < 8; i++) {
            int f  = tid + i * 256;      // [0,2048)
            int r  = f >> 4;
            int j  = f & 15;
            int gr = row0 + r;
            uint4 v = make_uint4(0u, 0u, 0u, 0u);
            if (gr < n) v = Xg[gr * 16 + j];
            *reinterpret_cast<uint4*>(&Xs[r * SPADW + j * 4]) = v;
            *reinterpret_cast<uint4*>(&Ws[r * SPADW + j * 4]) = Wg[f];
        }
    }
    __syncthreads();

    const int lane = tid & 31;
    const int warp = tid >> 5;
    const int m0   = (warp & 3) * 32;
    const int nc0  = (warp >> 2) * 64;
    const int r    = lane >> 2;
    const int c    = lane & 3;

    float acc0[8][4];
    float acc1[8][4];
    #pragma unroll
    for (int nt = 0; nt < 8; nt++)
        #pragma unroll
        for (int j = 0; j < 4; j++) { acc0[nt][j] = 0.0f; acc1[nt][j] = 0.0f; }

    #pragma unroll
    for (int sg = 0; sg < 4; sg++) {
        const int kb = sg * 16 + c * 4;
        uint4 A0 = *reinterpret_cast<const uint4*>(&Xs[(m0 + r     ) * SPADW + kb]);
        uint4 A1 = *reinterpret_cast<const uint4*>(&Xs[(m0 + r +  8) * SPADW + kb]);
        uint4 A2 = *reinterpret_cast<const uint4*>(&Xs[(m0 + r + 16) * SPADW + kb]);
        uint4 A3 = *reinterpret_cast<const uint4*>(&Xs[(m0 + r + 24) * SPADW + kb]);
        #pragma unroll
        for (int nt = 0; nt < 8; nt++) {
            uint4 B = *reinterpret_cast<const uint4*>(&Ws[(nc0 + nt * 8 + r) * SPADW + kb]);
            mma_f16(acc0[nt], A0.x, A1.x, A0.y, A1.y, B.x, B.y);
            mma_f16(acc1[nt], A2.x, A3.x, A2.y, A3.y, B.x, B.y);
            mma_f16(acc0[nt], A0.z, A1.z, A0.w, A1.w, B.z, B.w);
            mma_f16(acc1[nt], A2.z, A3.z, A2.w, A3.w, B.z, B.w);
        }
    }

    const float* bias = (mat == 0) ? bA : (mat == 1) ? bB : (mat == 2) ? bD : bE;
    const float osc = (mat >= 2) ? 0.5f : 1.0f;
    #pragma unroll
    for (int mt = 0; mt < 2; mt++) {
        float (*acc)[4] = mt ? acc1 : acc0;
        const int gr0 = row0 + m0 + mt * 16 + r;
        const int gr1 = gr0 + 8;
        #pragma unroll
        for (int nt = 0; nt < 8; nt++) {
            int col = nc0 + nt * 8 + c * 2;
            float2 bv = *reinterpret_cast<const float2*>(&bias[col]);
            float2 o0 = make_float2((acc[nt][0] + bv.x) * osc, (acc[nt][1] + bv.y) * osc);
            float2 o1 = make_float2((acc[nt][2] + bv.x) * osc, (acc[nt][3] + bv.y) * osc);
            if (mat == 0) {
                if (gr0 < n) *reinterpret_cast<float2*>(&g_AX[gr0 * D + col]) = o0;
                if (gr1 < n) *reinterpret_cast<float2*>(&g_AX[gr1 * D + col]) = o1;
            } else if (mat == 3) {
                if (gr0 < n) *reinterpret_cast<__half2*>(&g_EXh[gr0 * D + col]) = __floats2half2_rn(o0.x, o0.y);
                if (gr1 < n) *reinterpret_cast<__half2*>(&g_EXh[gr1 * D + col]) = __floats2half2_rn(o1.x, o1.y);
            } else {
                int po = ((col >> 2) << 3) + (col & 3) + (mat == 1 ? 4 : 0);
                if (gr0 < n) *reinterpret_cast<__half2*>(&g_DBh[gr0 * 2 * D + po]) = __floats2half2_rn(o0.x, o0.y);
                if (gr1 < n) *reinterpret_cast<__half2*>(&g_DBh[gr1 * 2 * D + po]) = __floats2half2_rn(o1.x, o1.y);
            }
        }
    }
}

// ---------------- side kernels 5-9: CSR build (hist -> scan -> scatter) -------
__global__ void hist_kernel(const int* __restrict__ dst, int E) {
    int e = blockIdx.x * blockDim.x + threadIdx.x;
    if (e < E) atomicAdd(&g_cnt[dst[e]], 1);
}

__global__ void scan1_kernel(int n) {
    __shared__ int s[SCAN_BLK];
    int tid = threadIdx.x;
    int i = blockIdx.x * SCAN_BLK + tid;
    s[tid] = (i < n) ? g_cnt[i] : 0;
    __syncthreads();
    for (int d = SCAN_BLK / 2; d > 0; d >>= 1) {
        if (tid < d) s[tid] += s[tid + d];
        __syncthreads();
    }
    if (tid == 0) g_bsum[blockIdx.x] = s[0];
}

__global__ void scan2_kernel(int nblk) {
    __shared__ int s[64];
    int tid = threadIdx.x;
    int v = (tid < nblk) ? g_bsum[tid] : 0;
    s[tid] = v;
    __syncthreads();
    for (int d = 1; d < 64; d <<= 1) {
        int t = (tid >= d) ? s[tid - d] : 0;
        __syncthreads();
        s[tid] += t;
        __syncthreads();
    }
    if (tid < nblk) g_bpre[tid] = s[tid] - v;
}

__global__ void scan3_kernel(int n) {
    __shared__ int s[SCAN_BLK];
    int tid = threadIdx.x;
    int i = blockIdx.x * SCAN_BLK + tid;
    int v = (i < n) ? g_cnt[i] : 0;
    s[tid] = v;
    __syncthreads();
    for (int d = 1; d < SCAN_BLK; d <<= 1) {
        int t = (tid >= d) ? s[tid - d] : 0;
        __syncthreads();
        s[tid] += t;
        __syncthreads();
    }
    if (i < n) {
        g_off[i] = g_bpre[blockIdx.x] + s[tid] - v;  // exclusive
        g_cnt[i] = 0;                                // reset as scatter cursor
    }
}

__global__ void scatter_kernel(const int* __restrict__ src,
                               const int* __restrict__ dst, int E)
{
    int e = blockIdx.x * blockDim.x + threadIdx.x;
    if (e < E) {
        int d0 = dst[e];
        int pos = g_off[d0] + atomicAdd(&g_cnt[d0], 1);
        g_csr[pos] = src[e] * (2 * D * (int)sizeof(__half));   // byte offset
    }
}

// ---------------- kernel 10 (main): aggregation + H(fp16) + BN partials -------
__global__ __launch_bounds__(256, 5) void agg_kernel(const float* __restrict__ X, int n)
{
    __shared__ float ssum[D];
    __shared__ float ssq [D];
    const int tid = threadIdx.x;
    if (tid < D) { ssum[tid] = 0.0f; ssq[tid] = 0.0f; }
    __syncthreads();

    const __half2 h05 = __floats2half2_rn(0.5f, 0.5f);
    const int lane = tid & 31;
    const int warp = tid >> 5;
    const int off  = lane * 4;
    const char* dbbase = reinterpret_cast<const char*>(g_DBh) + lane * 16;
    const int gw   = blockIdx.x * 8 + warp;
    const int nw   = gridDim.x * 8;

    float4 csum = make_float4(0.f, 0.f, 0.f, 0.f);
    float4 csq  = make_float4(0.f, 0.f, 0.f, 0.f);

    for (int node = gw; node < n; node += nw) {
        int beg = g_off[node];
        int end = g_off[node + 1];
        int base = node * D + off;
        float4 h;
        if (end > beg) {
            uint2 eu = *reinterpret_cast<const uint2*>(&g_EXh[base]);
            __half2 e0 = u2h2(eu.x), e1 = u2h2(eu.y);
            float2 num0 = make_float2(0.f, 0.f), num1 = make_float2(0.f, 0.f);
            float2 den0 = make_float2(0.f, 0.f), den1 = make_float2(0.f, 0.f);
            int j = beg;
            int c0 = 0, c1 = 0, c2 = 0, c3 = 0;
            if (j + 3 < end) {
                c0 = g_csr[j]; c1 = g_csr[j + 1]; c2 = g_csr[j + 2]; c3 = g_csr[j + 3];
            }
            while (j + 3 < end) {
                int p0 = 0, p1 = 0, p2 = 0, p3 = 0;
                if (j + 7 < end) {
                    p0 = g_csr[j + 4]; p1 = g_csr[j + 5];
                    p2 = g_csr[j + 6]; p3 = g_csr[j + 7];
                }
                uint4 q0 = *reinterpret_cast<const uint4*>(dbbase + c0);
                uint4 q1 = *reinterpret_cast<const uint4*>(dbbase + c1);
                uint4 q2 = *reinterpret_cast<const uint4*>(dbbase + c2);
                uint4 q3 = *reinterpret_cast<const uint4*>(dbbase + c3);
                __half2 sg00 = gate2(q0.x, e0, h05), sg01 = gate2(q0.y, e1, h05);
                __half2 sg10 = gate2(q1.x, e0, h05), sg11 = gate2(q1.y, e1, h05);
                __half2 sg20 = gate2(q2.x, e0, h05), sg21 = gate2(q2.y, e1, h05);
                __half2 sg30 = gate2(q3.x, e0, h05), sg31 = gate2(q3.y, e1, h05);
                __half2 hd0 = __hadd2(__hadd2(sg00, sg10), __hadd2(sg20, sg30));
                __half2 hd1 = __hadd2(__hadd2(sg01, sg11), __hadd2(sg21, sg31));
                __half2 hn0 = __hadd2(__hadd2(__hmul2(sg00, u2h2(q0.z)), __hmul2(sg10, u2h2(q1.z))),
                                      __hadd2(__hmul2(sg20, u2h2(q2.z)), __hmul2(sg30, u2h2(q3.z))));
                __half2 hn1 = __hadd2(__hadd2(__hmul2(sg01, u2h2(q0.w)), __hmul2(sg11, u2h2(q1.w))),
                                      __hadd2(__hmul2(sg21, u2h2(q2.w)), __hmul2(sg31, u2h2(q3.w))));
                float2 f;
                f = __half22float2(hd0); den0.x += f.x; den0.y += f.y;
                f = __half22float2(hd1); den1.x += f.x; den1.y += f.y;
                f = __half22float2(hn0); num0.x += f.x; num0.y += f.y;
                f = __half22float2(hn1); num1.x += f.x; num1.y += f.y;
                c0 = p0; c1 = p1; c2 = p2; c3 = p3;
                j += 4;
            }
            for (; j < end; j++) {
                int s = g_csr[j];
                uint4 q = *reinterpret_cast<const uint4*>(dbbase + s);
                __half2 sg0 = gate2(q.x, e0, h05), sg1 = gate2(q.y, e1, h05);
                float2 f;
                f = __half22float2(sg0); den0.x += f.x; den0.y += f.y;
                f = __half22float2(sg1); den1.x += f.x; den1.y += f.y;
                f = __half22float2(__hmul2(sg0, u2h2(q.z))); num0.x += f.x; num0.y += f.y;
                f = __half22float2(__hmul2(sg1, u2h2(q.w))); num1.x += f.x; num1.y += f.y;
            }
            float4 ax = *reinterpret_cast<const float4*>(&g_AX[base]);
            h.x = ax.x + num0.x / den0.x;
            h.y = ax.y + num0.y / den0.y;
            h.z = ax.z + num1.x / den1.x;
            h.w = ax.w + num1.y / den1.y;
        } else {
            h = *reinterpret_cast<const float4*>(&X[base]);
        }
        // store H as fp16
        __half2 hh0 = __floats2half2_rn(h.x, h.y);
        __half2 hh1 = __floats2half2_rn(h.z, h.w);
        *reinterpret_cast<uint2*>(&g_Hh[base]) =
            make_uint2(*reinterpret_cast<uint32_t*>(&hh0),
                       *reinterpret_cast<uint32_t*>(&hh1));
        csum.x += h.x; csum.y += h.y; csum.z += h.z; csum.w += h.w;
        csq.x  = fmaf(h.x, h.x, csq.x);
        csq.y  = fmaf(h.y, h.y, csq.y);
        csq.z  = fmaf(h.z, h.z, csq.z);
        csq.w  = fmaf(h.w, h.w, csq.w);
    }

    atomicAdd(&ssum[off + 0], csum.x); atomicAdd(&ssum[off + 1], csum.y);
    atomicAdd(&ssum[off + 2], csum.z); atomicAdd(&ssum[off + 3], csum.w);
    atomicAdd(&ssq [off + 0], csq.x);  atomicAdd(&ssq [off + 1], csq.y);
    atomicAdd(&ssq [off + 2], csq.z);  atomicAdd(&ssq [off + 3], csq.w);
    __syncthreads();
    if (tid < D) {
        atomicAdd(&g_colsum[tid], ssum[tid]);
        atomicAdd(&g_colsq [tid], ssq [tid]);
    }
}

// ---------------- kernel 11 (main): epilogue with inline BN stats -------------
__global__ __launch_bounds__(256) void final_kernel(
    const float* __restrict__ X, const float* __restrict__ gamma,
    const float* __restrict__ beta, float* __restrict__ out,
    int n, float inv_n, float eps_n2)
{
    __shared__ float sc[D];
    __shared__ float sh[D];
    if (threadIdx.x < D) {
        int d = threadIdx.x;
        float mean = g_colsum[d] * inv_n;
        float var  = g_colsq[d] * inv_n - mean * mean;
        float istd = rsqrtf(var + eps_n2);
        float s    = istd * gamma[d];
        sc[d] = s;
        sh[d] = beta[d] - mean * s;
    }
    __syncthreads();

    int total4 = n * (D / 4);
    const float4* X4 = reinterpret_cast<const float4*>(X);
    const uint2*  H2 = reinterpret_cast<const uint2*>(g_Hh);
    float4* O4 = reinterpret_cast<float4*>(out);

    int tid = blockIdx.x * blockDim.x + threadIdx.x;
    int stride = gridDim.x * blockDim.x;
    for (int i = tid; i < total4; i += stride) {
        int d = (i & 31) * 4;
        uint2 hu = H2[i];
        float2 ha = __half22float2(u2h2(hu.x));
        float2 hb = __half22float2(u2h2(hu.y));
        float4 x = X4[i];
        float4 o;
        o.x = x.x + fmaxf(0.0f, fmaf(ha.x, sc[d + 0], sh[d + 0]));
        o.y = x.y + fmaxf(0.0f, fmaf(ha.y, sc[d + 1], sh[d + 1]));
        o.z = x.z + fmaxf(0.0f, fmaf(hb.x, sc[d + 2], sh[d + 2]));
        o.w = x.w + fmaxf(0.0f, fmaf(hb.y, sc[d + 3], sh[d + 3]));
        O4[i] = o;
    }
}

// ---------------- launch -----------------------------------------------------
extern "C" void kernel_launch(void* const* d_in, const int* in_sizes, int n_in,
                              void* d_out, int out_size)
{
    const float* X     = (const float*)d_in[0];
    const float* W_A   = (const float*)d_in[1];
    const float* b_A   = (const float*)d_in[2];
    const float* W_B   = (const float*)d_in[3];
    const float* b_B   = (const float*)d_in[4];
    const float* W_D   = (const float*)d_in[5];
    const float* b_D   = (const float*)d_in[6];
    const float* W_E   = (const float*)d_in[7];
    const float* b_E   = (const float*)d_in[8];
    const float* gamma = (const float*)d_in[9];
    const float* beta  = (const float*)d_in[10];
    const int*   src   = (const int*)d_in[11];
    const int*   dst   = (const int*)d_in[12];

    const int n = in_sizes[0] / D;
    const int E = in_sizes[11];
    const float inv_n  = 1.0f / (float)n;
    const float eps_n2 = 1e-5f * (float)n * (float)n;
    const int nblk = (n + SCAN_BLK - 1) / SCAN_BLK;

    // fork side stream
    cudaEventRecord(g_ctx.ev_fork, 0);
    cudaStreamWaitEvent(g_ctx.sb, g_ctx.ev_fork, 0);

    // side #1-#3: zero, weight prep, X conversion
    zero_kernel<<<128, 256, 0, g_ctx.sb>>>(n, E);
    prepw_kernel<<<dim3(4, 4, 4), dim3(32, 8), 0, g_ctx.sb>>>(W_A, W_B, W_D, W_E);
    prepx_kernel<<<296, 256, 0, g_ctx.sb>>>(X, n);
    cudaEventRecord(g_ctx.ev_prep, g_ctx.sb);

    // main #4 (profiled): fp16 GEMM — waits on prep
    cudaStreamWaitEvent(0, g_ctx.ev_prep, 0);
    static const int smem_bytes = 2 * 128 * SPADW * (int)sizeof(uint32_t);
    cudaFuncSetAttribute(gemm_kernel,
                         cudaFuncAttributeMaxDynamicSharedMemorySize, smem_bytes);
    gemm_kernel<<<dim3((n + 127) / 128, 4), 256, smem_bytes>>>(b_A, b_B, b_D, b_E, n);

    // side #5-#9: CSR build chain, hidden under GEMM
    hist_kernel<<<(E + 255) / 256, 256, 0, g_ctx.sb>>>(dst, E);
    scan1_kernel<<<nblk, SCAN_BLK, 0, g_ctx.sb>>>(n);
    scan2_kernel<<<1, 64, 0, g_ctx.sb>>>(nblk);
    scan3_kernel<<<nblk, SCAN_BLK, 0, g_ctx.sb>>>(n);
    scatter_kernel<<<(E + 255) / 256, 256, 0, g_ctx.sb>>>(src, dst, E);
    cudaEventRecord(g_ctx.ev_bB, g_ctx.sb);

    // main #10: aggregation — needs gemm (stream order) + CSR (event)
    cudaStreamWaitEvent(0, g_ctx.ev_bB, 0);
    agg_kernel<<<1480, 256>>>(X, n);

    // main #11: epilogue with inline stats
    final_kernel<<<1024, 256>>>(X, gamma, beta, (float*)d_out, n, inv_n, eps_n2);
}

// round 17
// speedup vs baseline: 1.0788x; 1.0530x over previous
#include <cuda_runtime.h>
#include <cuda_fp16.h>
#include <cstdint>

#define D 128
#define MAXN 50000
#define MAXE 800000
#define SCAN_BLK 1024

// ---------------- scratch (device globals; no allocations allowed) ----------
__device__ float  g_AX [MAXN * D];
__device__ __half g_DBh[MAXN * 2 * D];   // per node: 32 groups of [4x 0.5*D half | 4x B half]
__device__ __half g_EXh[MAXN * D];       // 0.5 * EX
__device__ __half g_WTh[4 * D * D];      // W^T, fp16, quad-packed words
__device__ __half g_Hh [MAXN * D];       // H, fp16
__device__ int    g_cnt[MAXN];
__device__ int    g_off[MAXN + 1];
__device__ int    g_csr[MAXE];           // BYTE offsets into g_DBh (src * 512)
__device__ int    g_bsum[64];
__device__ int    g_bpre[64];
__device__ float  g_colsum[D];
__device__ float  g_colsq [D];

// ---------------- static stream/event context (created at load, pre-capture) -
namespace {
struct Ctx {
    cudaStream_t sb;
    cudaEvent_t ev_fork, ev_prep, ev_bB;
    Ctx() {
        cudaStreamCreateWithFlags(&sb, cudaStreamNonBlocking);
        cudaEventCreateWithFlags(&ev_fork, cudaEventDisableTiming);
        cudaEventCreateWithFlags(&ev_prep, cudaEventDisableTiming);
        cudaEventCreateWithFlags(&ev_bB, cudaEventDisableTiming);
    }
};
Ctx g_ctx;
}

// ---------------- helpers ----------------------------------------------------
__device__ __forceinline__ __half2 u2h2(uint32_t u) {
    return *reinterpret_cast<__half2*>(&u);
}
// sigmoid(2x) for packed half2 x: 0.5*tanh(x)+0.5 (inputs pre-scaled by 0.5)
__device__ __forceinline__ __half2 gate2(uint32_t dh, __half2 e, __half2 h05) {
    __half2 s = __hadd2(u2h2(dh), e);
    uint32_t t;
    asm("tanh.approx.f16x2 %0, %1;" : "=r"(t) : "r"(*reinterpret_cast<uint32_t*>(&s)));
    return __hfma2(u2h2(t), h05, h05);
}
// quad-packed physical position of half2-word w within its 16-word supergroup
__device__ __forceinline__ int qposw(int w) {
    return ((w >> 4) << 4) + ((w & 3) << 2) + ((w >> 2) & 3);
}
// physical HALF index for logical k (word = k/2, lane = k%2)
__device__ __forceinline__ int qposh(int k) {
    return (qposw(k >> 1) << 1) + (k & 1);
}
__device__ __forceinline__ void mma_f16(float* a4,
                                        uint32_t a0, uint32_t a1, uint32_t a2, uint32_t a3,
                                        uint32_t b0, uint32_t b1) {
    asm volatile(
        "mma.sync.aligned.m16n8k16.row.col.f32.f16.f16.f32 "
        "{%0,%1,%2,%3}, {%4,%5,%6,%7}, {%8,%9}, {%0,%1,%2,%3};"
        : "+f"(a4[0]), "+f"(a4[1]), "+f"(a4[2]), "+f"(a4[3])
        : "r"(a0), "r"(a1), "r"(a2), "r"(a3), "r"(b0), "r"(b1));
}

// ---------------- kernel 1 (side): transpose + fp16 + quad-pack weights -------
__global__ void prepw_kernel(const float* __restrict__ WA, const float* __restrict__ WB,
                             const float* __restrict__ WD, const float* __restrict__ WE)
{
    __shared__ float t[32][33];
    const float* W;
    switch (blockIdx.z) {
        case 0:  W = WA; break;
        case 1:  W = WB; break;
        case 2:  W = WD; break;
        default: W = WE; break;
    }
    int n0 = blockIdx.x * 32;
    int k0 = blockIdx.y * 32;
    for (int i = threadIdx.y; i < 32; i += 8)
        t[i][threadIdx.x] = W[(k0 + i) * D + n0 + threadIdx.x];
    __syncthreads();
    __half* out = g_WTh + blockIdx.z * D * D;
    for (int i = threadIdx.y; i < 32; i += 8) {
        float v = t[threadIdx.x][i];                 // W[k0+tx][n0+i]
        out[(n0 + i) * D + qposh(k0 + threadIdx.x)] = __float2half_rn(v);
    }
}

// ---------------- kernel 2 (side): zero counters + BN partials ----------------
__global__ void zero_kernel(int n, int E) {
    int tid = blockIdx.x * blockDim.x + threadIdx.x;
    int stride = gridDim.x * blockDim.x;
    for (int i = tid; i < n; i += stride) g_cnt[i] = 0;
    if (tid < D) { g_colsum[tid] = 0.0f; g_colsq[tid] = 0.0f; }
    if (tid == 0) g_off[n] = E;
}

// ---------------- kernel 3 (side): histogram ----------------------------------
__global__ void hist_kernel(const int* __restrict__ dst, int E) {
    int e = blockIdx.x * blockDim.x + threadIdx.x;
    if (e < E) atomicAdd(&g_cnt[dst[e]], 1);
}

// ---------------- kernel 4 (PROFILED, main): fp16 tensor GEMM -----------------
// X loaded fp32 from global, converted+quad-packed inline.
#define SPADW 80
__global__ __launch_bounds__(256, 2) void gemm_kernel(
    const float* __restrict__ X,
    const float* __restrict__ bA, const float* __restrict__ bB,
    const float* __restrict__ bD, const float* __restrict__ bE,
    int n)
{
    extern __shared__ uint32_t smw[];
    uint32_t* Xs = smw;                // [128][SPADW] half2 words
    uint32_t* Ws = smw + 128 * SPADW;

    const int tid  = threadIdx.x;
    const int mat  = blockIdx.y;
    const int row0 = blockIdx.x * 128;

    // X tile: fp32 load + cvt to half2 quad-packed
    {
        const float4* Xg = reinterpret_cast<const float4*>(X);
        #pragma unroll
        for (int i = 0; i < 16; i++) {
            int f  = tid + i * 256;      // [0,4096) float4s
            int r  = f >> 5;             // row 0..127
            int c4 = f & 31;             // float4 idx
            int gr = row0 + r;
            float4 v = make_float4(0.f, 0.f, 0.f, 0.f);
            if (gr < n) v = Xg[gr * 32 + c4];
            __half2 h0 = __floats2half2_rn(v.x, v.y);
            __half2 h1 = __floats2half2_rn(v.z, v.w);
            int base = r * SPADW;
            Xs[base + qposw(c4 * 2    )] = *reinterpret_cast<uint32_t*>(&h0);
            Xs[base + qposw(c4 * 2 + 1)] = *reinterpret_cast<uint32_t*>(&h1);
        }
    }
    // W tile (pre-packed): 128 rows x 16 uint4
    {
        const uint4* Wg = reinterpret_cast<const uint4*>(g_WTh + mat * D * D);
        #pragma unroll
        for (int i = 0; i < 8; i++) {
            int f  = tid + i * 256;
            int r  = f >> 4;
            int j  = f & 15;
            *reinterpret_cast<uint4*>(&Ws[r * SPADW + j * 4]) = Wg[f];
        }
    }
    __syncthreads();

    const int lane = tid & 31;
    const int warp = tid >> 5;
    const int m0   = (warp & 3) * 32;
    const int nc0  = (warp >> 2) * 64;
    const int r    = lane >> 2;
    const int c    = lane & 3;

    float acc0[8][4];
    float acc1[8][4];
    #pragma unroll
    for (int nt = 0; nt < 8; nt++)
        #pragma unroll
        for (int j = 0; j < 4; j++) { acc0[nt][j] = 0.0f; acc1[nt][j] = 0.0f; }

    #pragma unroll
    for (int sg = 0; sg < 4; sg++) {
        const int kb = sg * 16 + c * 4;
        uint4 A0 = *reinterpret_cast<const uint4*>(&Xs[(m0 + r     ) * SPADW + kb]);
        uint4 A1 = *reinterpret_cast<const uint4*>(&Xs[(m0 + r +  8) * SPADW + kb]);
        uint4 A2 = *reinterpret_cast<const uint4*>(&Xs[(m0 + r + 16) * SPADW + kb]);
        uint4 A3 = *reinterpret_cast<const uint4*>(&Xs[(m0 + r + 24) * SPADW + kb]);
        #pragma unroll
        for (int nt = 0; nt < 8; nt++) {
            uint4 B = *reinterpret_cast<const uint4*>(&Ws[(nc0 + nt * 8 + r) * SPADW + kb]);
            mma_f16(acc0[nt], A0.x, A1.x, A0.y, A1.y, B.x, B.y);
            mma_f16(acc1[nt], A2.x, A3.x, A2.y, A3.y, B.x, B.y);
            mma_f16(acc0[nt], A0.z, A1.z, A0.w, A1.w, B.z, B.w);
            mma_f16(acc1[nt], A2.z, A3.z, A2.w, A3.w, B.z, B.w);
        }
    }

    const float* bias = (mat == 0) ? bA : (mat == 1) ? bB : (mat == 2) ? bD : bE;
    const float osc = (mat >= 2) ? 0.5f : 1.0f;
    #pragma unroll
    for (int mt = 0; mt < 2; mt++) {
        float (*acc)[4] = mt ? acc1 : acc0;
        const int gr0 = row0 + m0 + mt * 16 + r;
        const int gr1 = gr0 + 8;
        #pragma unroll
        for (int nt = 0; nt < 8; nt++) {
            int col = nc0 + nt * 8 + c * 2;
            float2 bv = *reinterpret_cast<const float2*>(&bias[col]);
            float2 o0 = make_float2((acc[nt][0] + bv.x) * osc, (acc[nt][1] + bv.y) * osc);
            float2 o1 = make_float2((acc[nt][2] + bv.x) * osc, (acc[nt][3] + bv.y) * osc);
            if (mat == 0) {
                if (gr0 < n) *reinterpret_cast<float2*>(&g_AX[gr0 * D + col]) = o0;
                if (gr1 < n) *reinterpret_cast<float2*>(&g_AX[gr1 * D + col]) = o1;
            } else if (mat == 3) {
                if (gr0 < n) *reinterpret_cast<__half2*>(&g_EXh[gr0 * D + col]) = __floats2half2_rn(o0.x, o0.y);
                if (gr1 < n) *reinterpret_cast<__half2*>(&g_EXh[gr1 * D + col]) = __floats2half2_rn(o1.x, o1.y);
            } else {
                int po = ((col >> 2) << 3) + (col & 3) + (mat == 1 ? 4 : 0);
                if (gr0 < n) *reinterpret_cast<__half2*>(&g_DBh[gr0 * 2 * D + po]) = __floats2half2_rn(o0.x, o0.y);
                if (gr1 < n) *reinterpret_cast<__half2*>(&g_DBh[gr1 * 2 * D + po]) = __floats2half2_rn(o1.x, o1.y);
            }
        }
    }
}

// ---------------- side kernels: scans + scatter --------------------------------
__global__ void scan1_kernel(int n) {
    __shared__ int s[SCAN_BLK];
    int tid = threadIdx.x;
    int i = blockIdx.x * SCAN_BLK + tid;
    s[tid] = (i < n) ? g_cnt[i] : 0;
    __syncthreads();
    for (int d = SCAN_BLK / 2; d > 0; d >>= 1) {
        if (tid < d) s[tid] += s[tid + d];
        __syncthreads();
    }
    if (tid == 0) g_bsum[blockIdx.x] = s[0];
}

__global__ void scan2_kernel(int nblk) {
    __shared__ int s[64];
    int tid = threadIdx.x;
    int v = (tid < nblk) ? g_bsum[tid] : 0;
    s[tid] = v;
    __syncthreads();
    for (int d = 1; d < 64; d <<= 1) {
        int t = (tid >= d) ? s[tid - d] : 0;
        __syncthreads();
        s[tid] += t;
        __syncthreads();
    }
    if (tid < nblk) g_bpre[tid] = s[tid] - v;
}

__global__ void scan3_kernel(int n) {
    __shared__ int s[SCAN_BLK];
    int tid = threadIdx.x;
    int i = blockIdx.x * SCAN_BLK + tid;
    int v = (i < n) ? g_cnt[i] : 0;
    s[tid] = v;
    __syncthreads();
    for (int d = 1; d < SCAN_BLK; d <<= 1) {
        int t = (tid >= d) ? s[tid - d] : 0;
        __syncthreads();
        s[tid] += t;
        __syncthreads();
    }
    if (i < n) {
        g_off[i] = g_bpre[blockIdx.x] + s[tid] - v;  // exclusive
        g_cnt[i] = 0;                                // reset as scatter cursor
    }
}

__global__ void scatter_kernel(const int* __restrict__ src,
                               const int* __restrict__ dst, int E)
{
    int e = blockIdx.x * blockDim.x + threadIdx.x;
    if (e < E) {
        int d0 = dst[e];
        int pos = g_off[d0] + atomicAdd(&g_cnt[d0], 1);
        g_csr[pos] = src[e] * (2 * D * (int)sizeof(__half));   // byte offset
    }
}

// ---------------- kernel (main): aggregation + H(fp16) + BN partials ----------
__global__ __launch_bounds__(256, 5) void agg_kernel(const float* __restrict__ X, int n)
{
    __shared__ float ssum[D];
    __shared__ float ssq [D];
    const int tid = threadIdx.x;
    if (tid < D) { ssum[tid] = 0.0f; ssq[tid] = 0.0f; }
    __syncthreads();

    const __half2 h05 = __floats2half2_rn(0.5f, 0.5f);
    const int lane = tid & 31;
    const int warp = tid >> 5;
    const int off  = lane * 4;
    const char* dbbase = reinterpret_cast<const char*>(g_DBh) + lane * 16;
    const int gw   = blockIdx.x * 8 + warp;
    const int nw   = gridDim.x * 8;

    float4 csum = make_float4(0.f, 0.f, 0.f, 0.f);
    float4 csq  = make_float4(0.f, 0.f, 0.f, 0.f);

    for (int node = gw; node < n; node += nw) {
        int beg = g_off[node];
        int end = g_off[node + 1];
        int base = node * D + off;
        float4 h;
        if (end > beg) {
            uint2 eu = *reinterpret_cast<const uint2*>(&g_EXh[base]);
            __half2 e0 = u2h2(eu.x), e1 = u2h2(eu.y);
            float2 num0 = make_float2(0.f, 0.f), num1 = make_float2(0.f, 0.f);
            float2 den0 = make_float2(0.f, 0.f), den1 = make_float2(0.f, 0.f);
            int j = beg;
            int c0 = 0, c1 = 0, c2 = 0, c3 = 0;
            if (j + 3 < end) {
                c0 = g_csr[j]; c1 = g_csr[j + 1]; c2 = g_csr[j + 2]; c3 = g_csr[j + 3];
            }
            while (j + 3 < end) {
                int p0 = 0, p1 = 0, p2 = 0, p3 = 0;
                if (j + 7 < end) {
                    p0 = g_csr[j + 4]; p1 = g_csr[j + 5];
                    p2 = g_csr[j + 6]; p3 = g_csr[j + 7];
                }
                uint4 q0 = *reinterpret_cast<const uint4*>(dbbase + c0);
                uint4 q1 = *reinterpret_cast<const uint4*>(dbbase + c1);
                uint4 q2 = *reinterpret_cast<const uint4*>(dbbase + c2);
                uint4 q3 = *reinterpret_cast<const uint4*>(dbbase + c3);
                __half2 sg00 = gate2(q0.x, e0, h05), sg01 = gate2(q0.y, e1, h05);
                __half2 sg10 = gate2(q1.x, e0, h05), sg11 = gate2(q1.y, e1, h05);
                __half2 sg20 = gate2(q2.x, e0, h05), sg21 = gate2(q2.y, e1, h05);
                __half2 sg30 = gate2(q3.x, e0, h05), sg31 = gate2(q3.y, e1, h05);
                __half2 hd0 = __hadd2(__hadd2(sg00, sg10), __hadd2(sg20, sg30));
                __half2 hd1 = __hadd2(__hadd2(sg01, sg11), __hadd2(sg21, sg31));
                __half2 hn0 = __hadd2(__hadd2(__hmul2(sg00, u2h2(q0.z)), __hmul2(sg10, u2h2(q1.z))),
                                      __hadd2(__hmul2(sg20, u2h2(q2.z)), __hmul2(sg30, u2h2(q3.z))));
                __half2 hn1 = __hadd2(__hadd2(__hmul2(sg01, u2h2(q0.w)), __hmul2(sg11, u2h2(q1.w))),
                                      __hadd2(__hmul2(sg21, u2h2(q2.w)), __hmul2(sg31, u2h2(q3.w))));
                float2 f;
                f = __half22float2(hd0); den0.x += f.x; den0.y += f.y;
                f = __half22float2(hd1); den1.x += f.x; den1.y += f.y;
                f = __half22float2(hn0); num0.x += f.x; num0.y += f.y;
                f = __half22float2(hn1); num1.x += f.x; num1.y += f.y;
                c0 = p0; c1 = p1; c2 = p2; c3 = p3;
                j += 4;
            }
            for (; j < end; j++) {
                int s = g_csr[j];
                uint4 q = *reinterpret_cast<const uint4*>(dbbase + s);
                __half2 sg0 = gate2(q.x, e0, h05), sg1 = gate2(q.y, e1, h05);
                float2 f;
                f = __half22float2(sg0); den0.x += f.x; den0.y += f.y;
                f = __half22float2(sg1); den1.x += f.x; den1.y += f.y;
                f = __half22float2(__hmul2(sg0, u2h2(q.z))); num0.x += f.x; num0.y += f.y;
                f = __half22float2(__hmul2(sg1, u2h2(q.w))); num1.x += f.x; num1.y += f.y;
            }
            float4 ax = *reinterpret_cast<const float4*>(&g_AX[base]);
            h.x = ax.x + num0.x / den0.x;
            h.y = ax.y + num0.y / den0.y;
            h.z = ax.z + num1.x / den1.x;
            h.w = ax.w + num1.y / den1.y;
        } else {
            h = *reinterpret_cast<const float4*>(&X[base]);
        }
        __half2 hh0 = __floats2half2_rn(h.x, h.y);
        __half2 hh1 = __floats2half2_rn(h.z, h.w);
        *reinterpret_cast<uint2*>(&g_Hh[base]) =
            make_uint2(*reinterpret_cast<uint32_t*>(&hh0),
                       *reinterpret_cast<uint32_t*>(&hh1));
        csum.x += h.x; csum.y += h.y; csum.z += h.z; csum.w += h.w;
        csq.x  = fmaf(h.x, h.x, csq.x);
        csq.y  = fmaf(h.y, h.y, csq.y);
        csq.z  = fmaf(h.z, h.z, csq.z);
        csq.w  = fmaf(h.w, h.w, csq.w);
    }

    atomicAdd(&ssum[off + 0], csum.x); atomicAdd(&ssum[off + 1], csum.y);
    atomicAdd(&ssum[off + 2], csum.z); atomicAdd(&ssum[off + 3], csum.w);
    atomicAdd(&ssq [off + 0], csq.x);  atomicAdd(&ssq [off + 1], csq.y);
    atomicAdd(&ssq [off + 2], csq.z);  atomicAdd(&ssq [off + 3], csq.w);
    __syncthreads();
    if (tid < D) {
        atomicAdd(&g_colsum[tid], ssum[tid]);
        atomicAdd(&g_colsq [tid], ssq [tid]);
    }
}

// ---------------- kernel (main): epilogue with inline BN stats ----------------
__global__ __launch_bounds__(256) void final_kernel(
    const float* __restrict__ X, const float* __restrict__ gamma,
    const float* __restrict__ beta, float* __restrict__ out,
    int n, float inv_n, float eps_n2)
{
    __shared__ float sc[D];
    __shared__ float sh[D];
    if (threadIdx.x < D) {
        int d = threadIdx.x;
        float mean = g_colsum[d] * inv_n;
        float var  = g_colsq[d] * inv_n - mean * mean;
        float istd = rsqrtf(var + eps_n2);
        float s    = istd * gamma[d];
        sc[d] = s;
        sh[d] = beta[d] - mean * s;
    }
    __syncthreads();

    int total4 = n * (D / 4);
    const float4* X4 = reinterpret_cast<const float4*>(X);
    const uint2*  H2 = reinterpret_cast<const uint2*>(g_Hh);
    float4* O4 = reinterpret_cast<float4*>(out);

    int tid = blockIdx.x * blockDim.x + threadIdx.x;
    int stride = gridDim.x * blockDim.x;
    for (int i = tid; i < total4; i += stride) {
        int d = (i & 31) * 4;
        uint2 hu = H2[i];
        float2 ha = __half22float2(u2h2(hu.x));
        float2 hb = __half22float2(u2h2(hu.y));
        float4 x = X4[i];
        float4 o;
        o.x = x.x + fmaxf(0.0f, fmaf(ha.x, sc[d + 0], sh[d + 0]));
        o.y = x.y + fmaxf(0.0f, fmaf(ha.y, sc[d + 1], sh[d + 1]));
        o.z = x.z + fmaxf(0.0f, fmaf(hb.x, sc[d + 2], sh[d + 2]));
        o.w = x.w + fmaxf(0.0f, fmaf(hb.y, sc[d + 3], sh[d + 3]));
        O4[i] = o;
    }
}

// ---------------- launch -----------------------------------------------------
extern "C" void kernel_launch(void* const* d_in, const int* in_sizes, int n_in,
                              void* d_out, int out_size)
{
    const float* X     = (const float*)d_in[0];
    const float* W_A   = (const float*)d_in[1];
    const float* b_A   = (const float*)d_in[2];
    const float* W_B   = (const float*)d_in[3];
    const float* b_B   = (const float*)d_in[4];
    const float* W_D   = (const float*)d_in[5];
    const float* b_D   = (const float*)d_in[6];
    const float* W_E   = (const float*)d_in[7];
    const float* b_E   = (const float*)d_in[8];
    const float* gamma = (const float*)d_in[9];
    const float* beta  = (const float*)d_in[10];
    const int*   src   = (const int*)d_in[11];
    const int*   dst   = (const int*)d_in[12];

    const int n = in_sizes[0] / D;
    const int E = in_sizes[11];
    const float inv_n  = 1.0f / (float)n;
    const float eps_n2 = 1e-5f * (float)n * (float)n;
    const int nblk = (n + SCAN_BLK - 1) / SCAN_BLK;

    // fork side stream
    cudaEventRecord(g_ctx.ev_fork, 0);
    cudaStreamWaitEvent(g_ctx.sb, g_ctx.ev_fork, 0);

    // side #1: weight prep (gemm's ONLY dependency)
    prepw_kernel<<<dim3(4, 4, 4), dim3(32, 8), 0, g_ctx.sb>>>(W_A, W_B, W_D, W_E);
    cudaEventRecord(g_ctx.ev_prep, g_ctx.sb);

    // side #2, #3: zero + histogram
    zero_kernel<<<128, 256, 0, g_ctx.sb>>>(n, E);
    hist_kernel<<<(E + 255) / 256, 256, 0, g_ctx.sb>>>(dst, E);

    // main #4 (profiled): fp16 GEMM — waits only on prepw
    cudaStreamWaitEvent(0, g_ctx.ev_prep, 0);
    static const int smem_bytes = 2 * 128 * SPADW * (int)sizeof(uint32_t);
    cudaFuncSetAttribute(gemm_kernel,
                         cudaFuncAttributeMaxDynamicSharedMemorySize, smem_bytes);
    gemm_kernel<<<dim3((n + 127) / 128, 4), 256, smem_bytes>>>(X, b_A, b_B, b_D, b_E, n);

    // side #5-#8: scans + scatter, hidden under GEMM
    scan1_kernel<<<nblk, SCAN_BLK, 0, g_ctx.sb>>>(n);
    scan2_kernel<<<1, 64, 0, g_ctx.sb>>>(nblk);
    scan3_kernel<<<nblk, SCAN_BLK, 0, g_ctx.sb>>>(n);
    scatter_kernel<<<(E + 255) / 256, 256, 0, g_ctx.sb>>>(src, dst, E);
    cudaEventRecord(g_ctx.ev_bB, g_ctx.sb);

    // main: aggregation — needs gemm (stream order) + CSR (event)
    cudaStreamWaitEvent(0, g_ctx.ev_bB, 0);
    agg_kernel<<<1480, 256>>>(X, n);

    // main: epilogue with inline stats
    final_kernel<<<1024, 256>>>(X, gamma, beta, (float*)d_out, n, inv_n, eps_n2);
}